// round 14
// baseline (speedup 1.0000x reference)
#include <cuda_runtime.h>

#define NEGV  -1.0e8f
#define NCTA  32                 // 32 CTAs x 32 rows = 1024 rows
#define GW    1025               // boundary row: columns 0..1024
#define NGRP  129                // 129 groups x 8 steps = 1032; last active s=1030
#define RING  256                // per-warp bottom-row ring (cols mod 256)

// G[B][j] = V[32B][j] over 4 states (CTA-to-CTA boundary rows).
__device__ float4 G[(NCTA + 1) * GW];
// PROG[B*32] = highest column published into G[B]. Padded: one line per band.
__device__ int PROG[(NCTA + 1) * 32];

// ---------------------------------------------------------------------------
__global__ void init_kernel() {
    int i = threadIdx.x;
    if (i <= NCTA) PROG[i * 32] = 0;
}

// ---------------------------------------------------------------------------
__device__ __forceinline__ int ldacq_gpu(const int* p) {
    int v;
    asm volatile("ld.acquire.gpu.s32 %0, [%1];" : "=r"(v) : "l"(p) : "memory");
    return v;
}
__device__ __forceinline__ void strel_gpu(int* p, int v) {
    asm volatile("st.release.gpu.s32 [%0], %1;" :: "l"(p), "r"(v) : "memory");
}
__device__ __forceinline__ int ldacq_cta(const int* p) {
    int v;
    asm volatile("ld.acquire.cta.s32 %0, [%1];" : "=r"(v) : "l"(p) : "memory");
    return v;
}
__device__ __forceinline__ void strel_cta(int* p, int v) {
    asm volatile("st.release.cta.s32 [%0], %1;" :: "l"(p), "r"(v) : "memory");
}
// Plain coherent 16B global load (NOT .nc: G is written by peer CTAs).
__device__ __forceinline__ float4 ldg4(const float4* p) {
    float4 v;
    asm volatile("ld.global.v4.f32 {%0,%1,%2,%3}, [%4];"
                 : "=f"(v.x), "=f"(v.y), "=f"(v.z), "=f"(v.w) : "l"(p) : "memory");
    return v;
}

// ---------------------------------------------------------------------------
// Hierarchical persistent band DP, warp-only sync. Grid = 32 CTAs x 128 thr.
// Warp w (0..3) owns rows 32B + 8w + 1 .. +8. Lane = 4*a + t (cell a, state t).
// Cell a computes column j = s - a + 1 at step s (active s in [a, a+1023]).
// Engine (R8-proven): per-warp smem diag buffers, slot a+1 = cell a.
//   up (t=1): Pm1[a]  left (t=2): Pm1[a+1]  diag (t=0,3): Pm2[a]
// Cell a==0 halos: warp 0 from H0 ring (global row G[B], watermark-gated);
// warps 1-3 read producer warp's HS ring directly (col j at slot j & 255).
// Group g = steps 8g..8g+7 consumes halo cols 8g..8g+8. Producer publishes
// jmax = 8g+1 after its group g (release); consumer demands 8g+8 at start.
// All 8-step groups -> Ar[k]/Tr[k] constant-indexed (stays in registers).
// ---------------------------------------------------------------------------
__global__ __launch_bounds__(128) void dp_kernel(const float* __restrict__ theta,
                                                 const float4* __restrict__ A4) {
    __shared__ float4 D[4][3][10];         // per-warp diagonal buffers
    __shared__ float4 HS[3][RING];         // warp w in 0..2 bottom-row ring
    __shared__ float4 H0[32];              // warp 0 halo ring (from global)
    __shared__ int    WS[3];               // producer watermark (col)
    __shared__ int    CW[3];               // consumer progress (col)

    const int B    = blockIdx.x;
    const int tid  = threadIdx.x;
    const int w    = tid >> 5;
    const int lane = tid & 31;
    const int a    = lane >> 2;
    const int t    = lane & 3;
    const int r    = 32 * B + 8 * w + a;               // theta/A row = i-1
    const float4 NEG4 = make_float4(NEGV, NEGV, NEGV, NEGV);
    const float4* Grow = G + B * GW;                   // top boundary (warp 0)
    float*        Gout = (float*)(G + (B + 1) * GW);   // bottom row (warp 3)
    const int*    Pin  = PROG + B * 32;
    int*          Pout = PROG + (B + 1) * 32;

    // ---- smem init (the only CTA-wide barrier) ----
    if (tid < 4 * 3 * 10) ((float4*)D)[tid] = NEG4;    // left halo + pre-active
    if (tid < 3) { HS[tid][0] = NEG4; WS[tid] = 0; CW[tid] = 0; }  // col 0 = NEG
    __syncthreads();

    // ---- A/theta register ring, depth 8: slot k = data for step s, s&7==k ----
    float4 Ar[8]; float Tr[8];
    #pragma unroll
    for (int k = 0; k < 8; ++k) {
        int col = k - a; col = col < 0 ? 0 : col;
        int idx = (r * 1024 + col) * 4 + t;
        Ar[k] = __ldg(A4 + idx);
        Tr[k] = __ldg(theta + idx);
    }

    const bool bot      = (a == 7);
    const bool topCell  = (a == 0) && (t != 2);
    const bool flagLane = (lane == 28);                // a=7, t=0

    float4* Pn  = &D[w][0][0];
    float4* Pm1 = &D[w][2][0];
    float4* Pm2 = &D[w][1][0];

    for (int g = 0; g < NGRP; ++g) {
        // ================= group prologue =================
        if (w == 0) {
            // load halo cols 8g..8g+8 into H0 (watermark-gated for B>0)
            int base = 8 * g;
            if (base <= 1024) {
                if (B != 0) {
                    int need = base + 8; need = need > 1024 ? 1024 : need;
                    if (lane == 0) { int av = 0; while (av < need) av = ldacq_gpu(Pin); }
                    __syncwarp();                      // hb: acquire -> loads
                    if (lane <= 8) {
                        int p = base + lane;
                        if (p <= 1024)
                            H0[p & 31] = (p == 0) ? NEG4 : ldg4(Grow + p);
                    }
                } else {
                    if (lane <= 8) {
                        int p = base + lane;
                        if (p <= 1024)
                            H0[p & 31] = (p == 0) ? make_float4(0.f, 0.f, 0.f, 0.f)  // SEED
                                                  : NEG4;
                    }
                }
            }
            __syncwarp();
        } else {
            // wait until producer warp published cols up to 8g+8
            int need = 8 * g + 8; need = need > 1024 ? 1024 : need;
            if (lane == 0) { while (ldacq_cta(&WS[w - 1]) < need) {} }
            __syncwarp();                              // hb: acquire -> ring reads
        }

        // ================= 8 DP steps =================
        #pragma unroll
        for (int k = 0; k < 8; ++k) {
            const int s = 8 * g + k;
            float4 av = Ar[k];                         // constant index: registers
            float  tv = Tr[k];

            float4 s4;
            if (topCell) {
                if (w == 0) s4 = (t == 1) ? H0[(s + 1) & 31] : H0[s & 31];
                else        s4 = (t == 1) ? HS[w - 1][(s + 1) & (RING - 1)]
                                          : HS[w - 1][s & (RING - 1)];
            } else {
                const float4* sp = (t == 1) ? (Pm1 + a)
                                 : (t == 2) ? (Pm1 + a + 1)
                                            : (Pm2 + a);
                s4 = *sp;
            }

            float w0 = s4.x + av.x;
            float w1 = s4.y + av.y;
            float w2 = s4.z + av.z;
            float w3 = s4.w + av.w;
            float m = fmaxf(fmaxf(w0, w1), fmaxf(w2, w3));
            float sum = __expf(w0 - m) + __expf(w1 - m) +
                        __expf(w2 - m) + __expf(w3 - m);
            float res = m + __logf(sum) + tv;

            bool active = (s >= a) && (s <= a + 1023);
            if (active) {
                ((float*)(Pn + a + 1))[t] = res;
                if (bot) {                             // column j = s - 6 (>= 1)
                    int j = s - 6;
                    if (w == 3) Gout[j * 4 + t] = res;             // global row
                    else ((float*)&HS[w][j & (RING - 1)])[t] = res; // smem ring
                }
            }

            // refill A/theta ring for step s+8 (constant slot k)
            {
                int col = s + 8 - a;
                col = col < 0 ? 0 : (col > 1023 ? 1023 : col);
                int idx = (r * 1024 + col) * 4 + t;
                Ar[k] = __ldg(A4 + idx);
                Tr[k] = __ldg(theta + idx);
            }

            __syncwarp();   // orders all lanes' stores (hb for flags below)

            float4* tmp = Pm2; Pm2 = Pm1; Pm1 = Pn; Pn = tmp;
        }

        // ================= group epilogue =================
        int jmax = 8 * g + 1;                          // last col stored (j=s-6)
        if (w < 3) {
            if (flagLane) strel_cta(&WS[w], jmax > 1024 ? 1024 : jmax);
            // ring-overwrite safety: next group writes cols up to 8g+9; the
            // slot of col j also holds col j-RING -> need CW >= 8g+9-RING.
            int limit = 8 * g + 9 - RING;
            if (limit > 0) {
                if (flagLane) { while (((volatile int*)CW)[w] < limit) {} }
                __syncwarp();
            }
        } else {
            if (flagLane) strel_gpu(Pout, jmax > 1024 ? 1024 : jmax);
        }
        if (w >= 1 && flagLane) {
            int c = 8 * g + 8;                         // cols consumed through g
            ((volatile int*)CW)[w - 1] = c > 1024 ? 1024 : c;
        }
        __syncwarp();
    }
}

// ---------------------------------------------------------------------------
// Stream-ordered after dp_kernel: plain read is safe.
__global__ void final_kernel(float* out) {
    float4 v = ldg4(G + NCTA * GW + 1024);             // V[1024][1024]
    float m = fmaxf(fmaxf(v.x, v.y), fmaxf(v.z, v.w));
    out[0] = m + __logf(__expf(v.x - m) + __expf(v.y - m) +
                        __expf(v.z - m) + __expf(v.w - m));
}

// ---------------------------------------------------------------------------
extern "C" void kernel_launch(void* const* d_in, const int* in_sizes, int n_in,
                              void* d_out, int out_size) {
    const float*  theta = (const float*)d_in[0];   // [1024,1024,4]
    const float4* A4    = (const float4*)d_in[1];  // [1024,1024,4,4]

    init_kernel<<<1, 64>>>();
    dp_kernel<<<NCTA, 128>>>(theta, A4);
    final_kernel<<<1, 1>>>((float*)d_out);
}

// round 17
// speedup vs baseline: 1.1777x; 1.1777x over previous
#include <cuda_runtime.h>

#define NEGV  -1.0e8f
#define BH    32                 // band height (rows per CTA)
#define NB    32                 // number of bands
#define GW    1025               // boundary row: columns 0..1024
#define NGRP  132                // 132 groups x 8 steps; last active s=1054
#define LN2   0.69314718056f

// Cross-band boundary rows, LOG space (protocol identical to round 8).
__device__ float4 G[(NB + 1) * GW];
__device__ int    PROG[(NB + 1) * 32];
// Precomputed exp-space tables: EA = exp(A), ET = exp(theta).
__device__ float4 EAg[1024 * 1024 * 4];   // 64 MB
__device__ float  ETg[1024 * 1024 * 4];   // 16 MB

// ---------------------------------------------------------------------------
__global__ void init_kernel() {
    int i = threadIdx.x;
    if (i <= NB) PROG[i * 32] = 0;
}

// Streaming precompute: 4M threads, each one float4 of A (+ theta for i<1M).
__global__ void exp_kernel(const float4* __restrict__ A4,
                           const float4* __restrict__ T4) {
    int i = blockIdx.x * 256 + threadIdx.x;            // 0 .. 4M-1
    float4 a = A4[i];
    EAg[i] = make_float4(__expf(a.x), __expf(a.y), __expf(a.z), __expf(a.w));
    if (i < 1024 * 1024) {
        float4 t = T4[i];
        reinterpret_cast<float4*>(ETg)[i] =
            make_float4(__expf(t.x), __expf(t.y), __expf(t.z), __expf(t.w));
    }
}

// ---------------------------------------------------------------------------
__device__ __forceinline__ int ldacq_gpu(const int* p) {
    int v;
    asm volatile("ld.acquire.gpu.s32 %0, [%1];" : "=r"(v) : "l"(p) : "memory");
    return v;
}
__device__ __forceinline__ void strel_gpu(int* p, int v) {
    asm volatile("st.release.gpu.s32 [%0], %1;" :: "l"(p), "r"(v) : "memory");
}
__device__ __forceinline__ float4 ldg4(const float4* p) {
    float4 v;
    asm volatile("ld.global.v4.f32 {%0,%1,%2,%3}, [%4];"
                 : "=f"(v.x), "=f"(v.y), "=f"(v.z), "=f"(v.w) : "l"(p) : "memory");
    return v;
}

// ---------------------------------------------------------------------------
// Round-8 topology; inner math in exp space (U = exp(V - S_band)).
// Grid = 32 CTAs x 128 threads; CTA B covers rows 32B+1..32B+32.
// Thread = 4*a + t. Cell a computes column j = s-a+1 at step s (active
// s in [a, a+1023]). Boundary NEG == U=0 exactly.
// Slots: D slot 0 = top halo (tid0 feeds h[k] per step), slot a+1 = cell a.
//   up (t=1): Pm1[a]  left (t=2): Pm1[a+1]  diag (t=0,3): Pm2[a]
// Epoch rule: rescale factor f (published at the k==7 barrier) applies at
// READ time where the source predates the current group: k==0 (all sources),
// k==1 (Pm2 sources). Halo h[k] converts log->exp with the CURRENT S.
// Scale policy: S tracks the running diagonal MAX (warp-reduced at k==6,
// published at k==7) => U <= ~e^44 between anchors: no overflow; underflow
// only for globally-negligible cells. Publishes clamp res to >= 1e-33 so
// G never contains +-Inf.
// ---------------------------------------------------------------------------
__global__ __launch_bounds__(128) void dp_kernel() {
    __shared__ float4 D[3][BH + 2];
    __shared__ float  smS, smf;
    __shared__ float  smMax[4];

    const int B   = blockIdx.x;
    const int tid = threadIdx.x;
    const int a   = tid >> 2;
    const int t   = tid & 3;
    const int r   = BH * B + a;                        // theta/A row = i-1
    const float4* Grow = G + B * GW;                   // top boundary (read)
    float*        Gout = (float*)(G + (B + 1) * GW);   // bottom row (write)
    const int*    Pin  = PROG + B * 32;
    int*          Pout = PROG + (B + 1) * 32;

    const float4 Z4 = make_float4(0.f, 0.f, 0.f, 0.f);

    if (tid < 3 * (BH + 2)) ((float4*)D)[tid] = Z4;    // boundaries/pre-active = 0
    __syncthreads();                                   // zero-init before seeding

    // EA/ET register ring, depth 8: slot k holds data for step s, s&7==k.
    float4 EAr[8]; float ETr[8];
    #pragma unroll
    for (int k = 0; k < 8; ++k) {
        int col = k - a; col = col < 0 ? 0 : col;
        int idx = (r * 1024 + col) * 4 + t;
        EAr[k] = __ldg(EAg + idx);
        ETr[k] = __ldg(ETg + idx);
    }

    // Seed. Roles at s=0: Pn=D[0], Pm1=D[2], Pm2=D[1].
    //   D[1][0] = halo(0), D[2][0] = halo(1). Scale anchored to the MAX
    //   state of the first incoming halo -> all exp <= 1.
    if (tid == 0) {
        smf = 1.f;
        if (B == 0) {
            smS = 0.f;
            D[1][0] = make_float4(1.f, 1.f, 1.f, 1.f); // SEED: exp(0-0)=1
            // D[2][0] stays 0  (V[0][1] = NEG)
        } else {
            int av = 0; while (av < 1) av = ldacq_gpu(Pin);
            float4 v1 = ldg4(Grow + 1);
            float S = fmaxf(fmaxf(v1.x, v1.y), fmaxf(v1.z, v1.w));
            smS = S;
            D[2][0] = make_float4(__expf(v1.x - S), __expf(v1.y - S),
                                  __expf(v1.z - S), __expf(v1.w - S));
            // D[1][0] stays 0  (V[32B][0] = left boundary NEG)
        }
    }
    __syncthreads();

    const bool bot      = (a == BH - 1);
    const bool usePrev2 = (t == 0) || (t == 3);
    const bool relLane  = (tid == 4 * (BH - 1));       // thread 124
    const int  warpId   = tid >> 5;
    const int  lane     = tid & 31;

    float4* Pn  = D[0];
    float4* Pm1 = D[2];
    float4* Pm2 = D[1];

    for (int g = 0; g < NGRP; ++g) {
        const float fg = smf;                          // epoch factor this group
        const float Sg = smS;                          // this group's scale

        // Prologue: tid0 fetches halo cols 8g+2..8g+9, converts with Sg.
        float4 h[8];
        if (tid == 0) {
            if (B != 0) {
                int need = 8 * g + 9; need = need > 1024 ? 1024 : need;
                int av = 0; while (av < need) av = ldacq_gpu(Pin);
                #pragma unroll
                for (int k = 0; k < 8; ++k) {
                    int p = 8 * g + 2 + k; p = p > 1024 ? 1024 : p;
                    float4 hl = ldg4(Grow + p);
                    h[k] = make_float4(__expf(hl.x - Sg), __expf(hl.y - Sg),
                                       __expf(hl.z - Sg), __expf(hl.w - Sg));
                }
            } else {
                #pragma unroll
                for (int k = 0; k < 8; ++k) h[k] = Z4;
            }
        }

        #pragma unroll
        for (int k = 0; k < 8; ++k) {
            const int s = 8 * g + k;
            float4 av = EAr[k];
            float  tv = ETr[k];

            const float4* sp = (t == 1) ? (Pm1 + a)        // up   V[i-1][j]
                             : (t == 2) ? (Pm1 + a + 1)    // left V[i][j-1]
                                        : (Pm2 + a);       // diag V[i-1][j-1]
            float4 s4 = *sp;

            // epoch correction (compile-time k): old-epoch sources get *= fg
            if (k == 0) { s4.x *= fg; s4.y *= fg; s4.z *= fg; s4.w *= fg; }
            if (k == 1 && usePrev2) { s4.x *= fg; s4.y *= fg; s4.z *= fg; s4.w *= fg; }

            float res = (s4.x * av.x + s4.y * av.y +
                         s4.z * av.z + s4.w * av.w) * tv;

            bool active = (s >= a) && (s <= a + 1023);
            if (active) {
                ((float*)(Pn + a + 1))[t] = res;
                if (bot)                                   // col j = s-30; never +-Inf
                    Gout[(s - (BH - 2)) * 4 + t] = __logf(fmaxf(res, 1e-33f)) + Sg;
            }

            // k==6: per-warp max of active res -> smMax (for next-group anchor)
            if (k == 6) {
                float mv = active ? res : 0.f;
                #pragma unroll
                for (int o = 16; o > 0; o >>= 1)
                    mv = fmaxf(mv, __shfl_xor_sync(0xFFFFFFFFu, mv, o));
                if (lane == 0) smMax[warpId] = mv;
            }

            // refill ring for step s+8
            {
                int col = s + 8 - a;
                col = col < 0 ? 0 : (col > 1023 ? 1023 : col);
                int idx = (r * 1024 + col) * 4 + t;
                EAr[k] = __ldg(EAg + idx);
                ETr[k] = __ldg(ETg + idx);
            }

            if (tid == 0) Pn[0] = h[k];                // halo(s+2) -> next Dm1[0]

            // k==7: designated thread publishes next group's rescale from the
            // diagonal max (smMax written at k==6, visible via k==6 barrier).
            if (k == 7 && tid == 120) {
                float u = fmaxf(fmaxf(smMax[0], smMax[1]),
                                fmaxf(smMax[2], smMax[3]));
                float e = 0.f;
                if (u > 0.f && isfinite(u)) {
                    e = rintf(log2f(u));
                    e = fminf(fmaxf(e, -60.f), 60.f);
                }
                smf = exp2f(-e);
                smS = Sg + e * LN2;
            }

            __syncthreads();

            float4* tmp = Pm2; Pm2 = Pm1; Pm1 = Pn; Pn = tmp;
        }

        // One gpu-scope release per group (after the group-end barrier).
        if (relLane) {
            int jmax = 8 * g + 7 - (BH - 2);           // = 8g - 23
            if (jmax >= 1) strel_gpu(Pout, jmax > 1024 ? 1024 : jmax);
        }
    }
}

// ---------------------------------------------------------------------------
// Stream-ordered after dp_kernel: plain read is safe. (G row NB is log-space.)
__global__ void final_kernel(float* out) {
    float4 v = ldg4(G + NB * GW + 1024);               // V[1024][1024]
    float m = fmaxf(fmaxf(v.x, v.y), fmaxf(v.z, v.w));
    out[0] = m + __logf(__expf(v.x - m) + __expf(v.y - m) +
                        __expf(v.z - m) + __expf(v.w - m));
}

// ---------------------------------------------------------------------------
extern "C" void kernel_launch(void* const* d_in, const int* in_sizes, int n_in,
                              void* d_out, int out_size) {
    const float4* T4 = (const float4*)d_in[0];     // theta [1024,1024,4]
    const float4* A4 = (const float4*)d_in[1];     // A     [1024,1024,4,4]

    init_kernel<<<1, 64>>>();
    exp_kernel<<<(1024 * 1024 * 4) / 256, 256>>>(A4, T4);
    dp_kernel<<<NB, 128>>>();
    final_kernel<<<1, 1>>>((float*)d_out);
}